// round 13
// baseline (speedup 1.0000x reference)
#include <cuda_runtime.h>
#include <cuda_bf16.h>

// CenterLoss: loss = (1/(B*C)) * sum_i ||x_i - centers[labels_i]||^2
// B=4096, C=20000, D=128. Gather + reduce, single launch.
//
// Structure: 512 blocks x 256 threads (8 warps), one row per warp (best
// measured grid). Cross-block reduction via fire-and-forget RED:
//  - every block issues red.relaxed.gpu.add.u64 with a packed packet
//    (ticket in bits [63:50], 16.34 fixed-point partial in bits [49:0]).
//    No return value -> blocks retire without waiting on the L2 RMW.
//  - block 0 polls the accumulator (relaxed 8B loads + __nanosleep) until
//    the ticket field == NBLOCKS, then writes the scaled output and resets
//    the accumulator with a plain store (sole accessor; next replay is
//    ordered by the kernel boundary).
// Integer adds are associative -> bit-exact deterministic across replays.
//
// Measured dead ends (12 rounds; do not revisit): __threadfence (CCTL.IVALL
// per block, +3us); acq_rel ticket + partials re-read (+2us); <=128 CTAs
// (+0.3..0.8us); per-warp atomics (4096 same-address RMWs, +2us); separate
// reduce kernel (second launch ~3.5us GPU-side).

#define CL_BATCH 4096
#define CL_FEAT 128
#define CL_NCLASSES 20000
#define CL_WARPS 8
#define CL_THREADS (CL_WARPS * 32)                 // 256
#define CL_ROWS_PER_BLOCK CL_WARPS                 // one row per warp
#define CL_NBLOCKS (CL_BATCH / CL_ROWS_PER_BLOCK)  // 512

#define CL_TICKET_SHIFT 50
#define CL_SUM_MASK ((1ULL << CL_TICKET_SHIFT) - 1ULL)
#define CL_FIXED_SCALE 65536.0f  // 2^16 fractional bits

__device__ unsigned long long cl_g_acc = 0ULL;

__global__ void __launch_bounds__(CL_THREADS) cl_fused_kernel(
    const float* __restrict__ x,
    const int* __restrict__ labels,
    const float* __restrict__ centers,
    float* __restrict__ out)
{
    const int warp = threadIdx.x >> 5;
    const int lane = threadIdx.x & 31;
    const int row = blockIdx.x * CL_ROWS_PER_BLOCK + warp;

    // Head of the dependent chain: issue ASAP (broadcast load, 1 sector).
    const int lab = __ldg(&labels[row]);

    const float4* __restrict__ xr = reinterpret_cast<const float4*>(x + (size_t)row * CL_FEAT);
    float4 xv = xr[lane];  // independent of label, overlaps its latency

    const float4* __restrict__ cr = reinterpret_cast<const float4*>(centers + (size_t)lab * CL_FEAT);
    float4 cv = cr[lane];  // one dependent trip after label

    float dx = xv.x - cv.x;
    float dy = xv.y - cv.y;
    float dz = xv.z - cv.z;
    float dw = xv.w - cv.w;
    float s = dx * dx + dy * dy + dz * dz + dw * dw;

    // warp reduction
    #pragma unroll
    for (int o = 16; o > 0; o >>= 1)
        s += __shfl_xor_sync(0xffffffffu, s, o);

    __shared__ float sm[CL_WARPS];
    if (lane == 0) sm[warp] = s;
    __syncthreads();

    if (warp == 0) {
        // Shuffle-tree reduce of the 8 per-warp sums (lanes 0..7).
        float t = (lane < CL_WARPS) ? sm[lane] : 0.0f;
        #pragma unroll
        for (int o = 4; o > 0; o >>= 1)
            t += __shfl_xor_sync(0xffffffffu, t, o);

        if (lane == 0) {
            // Block partial ~ 1.1e3 -> fixed ~ 7.5e7; 512 blocks ~ 3.9e10 << 2^50.
            unsigned long long pkt =
                (1ULL << CL_TICKET_SHIFT) | __float2ull_rn(t * CL_FIXED_SCALE);

            // Fire-and-forget: no return value, no retirement dependency.
            asm volatile("red.relaxed.gpu.global.add.u64 [%0], %1;"
                         :: "l"(&cl_g_acc), "l"(pkt) : "memory");

            if (blockIdx.x == 0) {
                // Poll until all NBLOCKS packets have landed. Relaxed 8B
                // loads are atomic; ticket and sum update together per RED.
                unsigned long long v;
                for (;;) {
                    asm volatile("ld.relaxed.gpu.global.u64 %0, [%1];"
                                 : "=l"(v) : "l"(&cl_g_acc) : "memory");
                    if ((v >> CL_TICKET_SHIFT) ==
                        (unsigned long long)CL_NBLOCKS) break;
                    __nanosleep(32);
                }
                unsigned long long total = v & CL_SUM_MASK;
                const float inv = 1.0f / ((float)CL_BATCH * (float)CL_NCLASSES);
                *out = (float)total * (1.0f / CL_FIXED_SCALE) * inv;
                // All REDs have landed (count full); sole accessor now.
                cl_g_acc = 0ULL;
            }
        }
    }
}

extern "C" void kernel_launch(void* const* d_in, const int* in_sizes, int n_in,
                              void* d_out, int out_size)
{
    const float* x       = (const float*)d_in[0];
    const int*   labels  = (const int*)d_in[1];
    const float* centers = (const float*)d_in[2];
    float* out = (float*)d_out;

    cl_fused_kernel<<<CL_NBLOCKS, CL_THREADS>>>(x, labels, centers, out);
}

// round 14
// speedup vs baseline: 1.0047x; 1.0047x over previous
#include <cuda_runtime.h>
#include <cuda_bf16.h>

// CenterLoss: loss = (1/(B*C)) * sum_i ||x_i - centers[labels_i]||^2
// B=4096, C=20000, D=128. Gather + reduce, single launch.
//
// FINAL KERNEL — best measured configuration across 13 experimental rounds
// (ncu kernel 5.31us, wall 6.62-6.66us; wall noise band +/-0.25us).
//
// Structure: 512 blocks x 256 threads (8 warps), one row per warp.
//  - label load heads the dependent chain; x row load overlaps it;
//    center gather follows one memory trip later. All float4-vectorized.
//  - warp shuffle reduce -> 8 partials in shared -> lane<8 shuffle tree.
//  - ONE relaxed u64 atomicAdd per block: ticket in bits [63:50],
//    16.34 fixed-point partial in bits [49:0]. Integer adds are associative
//    -> bit-exact deterministic across graph replays (rel_err = 0).
//  - Block drawing the last ticket holds the grand total in-register,
//    writes the scaled output, and resets the accumulator with a plain
//    store (sole accessor; next replay ordered by the kernel boundary).
//
// Measured dead ends (13 rounds; do not revisit):
//  - __threadfence: gpu-scope => CCTL.IVALL L1 flush per block (+3us tail).
//  - acq_rel ticket + partials-array re-read: +2us.
//  - <=128 CTAs (any thread count): rollout imbalance, +0.3..0.8us.
//  - per-warp atomics (4096 same-address RMWs): last ticket waits behind
//    the serialized LTS queue, +2us.
//  - fire-and-forget RED + block-0 poll: neutral kernel, longer drain.
//  - separate reduce kernel: second launch costs ~3.5us GPU-side.
// Floor analysis: per-kernel fixed cost ~3.5us (measured via trivial
// kernel), intrinsic work ~1.5us, graph-replay gap ~1.3us => converged.

#define CL_BATCH 4096
#define CL_FEAT 128
#define CL_NCLASSES 20000
#define CL_WARPS 8
#define CL_THREADS (CL_WARPS * 32)                 // 256
#define CL_ROWS_PER_BLOCK CL_WARPS                 // one row per warp
#define CL_NBLOCKS (CL_BATCH / CL_ROWS_PER_BLOCK)  // 512

#define CL_TICKET_SHIFT 50
#define CL_SUM_MASK ((1ULL << CL_TICKET_SHIFT) - 1ULL)
#define CL_FIXED_SCALE 65536.0f  // 2^16 fractional bits

__device__ unsigned long long cl_g_acc = 0ULL;

__global__ void __launch_bounds__(CL_THREADS) cl_fused_kernel(
    const float* __restrict__ x,
    const int* __restrict__ labels,
    const float* __restrict__ centers,
    float* __restrict__ out)
{
    const int warp = threadIdx.x >> 5;
    const int lane = threadIdx.x & 31;
    const int row = blockIdx.x * CL_ROWS_PER_BLOCK + warp;

    // Head of the dependent chain: issue ASAP (broadcast load, 1 sector).
    const int lab = __ldg(&labels[row]);

    const float4* __restrict__ xr = reinterpret_cast<const float4*>(x + (size_t)row * CL_FEAT);
    float4 xv = xr[lane];  // independent of label, overlaps its latency

    const float4* __restrict__ cr = reinterpret_cast<const float4*>(centers + (size_t)lab * CL_FEAT);
    float4 cv = cr[lane];  // one dependent trip after label

    float dx = xv.x - cv.x;
    float dy = xv.y - cv.y;
    float dz = xv.z - cv.z;
    float dw = xv.w - cv.w;
    float s = dx * dx + dy * dy + dz * dz + dw * dw;

    // warp reduction
    #pragma unroll
    for (int o = 16; o > 0; o >>= 1)
        s += __shfl_xor_sync(0xffffffffu, s, o);

    __shared__ float sm[CL_WARPS];
    if (lane == 0) sm[warp] = s;
    __syncthreads();

    if (warp == 0) {
        // Shuffle-tree reduce of the 8 per-warp sums (lanes 0..7).
        float t = (lane < CL_WARPS) ? sm[lane] : 0.0f;
        #pragma unroll
        for (int o = 4; o > 0; o >>= 1)
            t += __shfl_xor_sync(0xffffffffu, t, o);

        if (lane == 0) {
            // Block partial ~ 1.1e3 -> fixed ~ 7.5e7; 512 blocks ~ 3.9e10 << 2^50.
            unsigned long long pkt =
                (1ULL << CL_TICKET_SHIFT) | __float2ull_rn(t * CL_FIXED_SCALE);

            unsigned long long old = atomicAdd(&cl_g_acc, pkt);

            if ((old >> CL_TICKET_SHIFT) == (unsigned long long)(CL_NBLOCKS - 1)) {
                unsigned long long total = (old + pkt) & CL_SUM_MASK;
                const float inv = 1.0f / ((float)CL_BATCH * (float)CL_NCLASSES);
                *out = (float)total * (1.0f / CL_FIXED_SCALE) * inv;
                // Sole accessor at this point; plain store resets for replay.
                cl_g_acc = 0ULL;
            }
        }
    }
}

extern "C" void kernel_launch(void* const* d_in, const int* in_sizes, int n_in,
                              void* d_out, int out_size)
{
    const float* x       = (const float*)d_in[0];
    const int*   labels  = (const int*)d_in[1];
    const float* centers = (const float*)d_in[2];
    float* out = (float*)d_out;

    cl_fused_kernel<<<CL_NBLOCKS, CL_THREADS>>>(x, labels, centers, out);
}